// round 9
// baseline (speedup 1.0000x reference)
#include <cuda_runtime.h>
#include <math.h>

#define N_ENT 200000
#define N_USR 100000
#define D     64
#define NEDGE 1500000
#define NINT  1000000
#define NVIRT 3
#define NRELM1 10
#define NBKT  (NVIRT * N_ENT)
#define NBKT_ALL (NBKT + N_USR)          // joint bucket space (entity then user)
#define NVAL_ALL (NEDGE + NINT)          // joint CSR value space
#define EPSV  1e-12f
#define SCAN_B 1024
#define CAP_E 12
#define CAP_U 12

// ---------------- scratch (static device globals; zero-initialized) ----------
__device__ float g_entB[(size_t)N_ENT * D];
__device__ float g_entC[(size_t)N_ENT * D];
__device__ float g_usrB[(size_t)N_USR * D];
__device__ float g_usrC[(size_t)N_USR * D];
__device__ int   g_csr[NVAL_ALL];        // entity tails then user items (joint)
__device__ int   g_cnt[NBKT_ALL];        // joint counts   (zeroed by tail of last hop)
__device__ int   g_off[NBKT_ALL + 1];    // joint exclusive-scan offsets
__device__ int   g_cur[NBKT_ALL];        // scatter cursors (zeroed by tail of last hop)
__device__ int   g_bsum[2048];
__device__ float g_w[2 * 3];             // softmaxed agg weights per hop

// ---------------- fused count: inline remap, entities + users, + softmax -----
__global__ void k_count(const int* __restrict__ head, const int* __restrict__ etype,
                        const int* __restrict__ uidx,
                        const float* __restrict__ latent, const float* __restrict__ relw,
                        const float* __restrict__ aggw) {
    __shared__ int srm[NRELM1];
    if (threadIdx.x < NRELM1) {
        int t = threadIdx.x;
        float best = -1e30f; int bi = 0;
        for (int v = 0; v < NVIRT; v++) {
            float s = 0.f;
            for (int d = 0; d < D; d++) s += relw[t * D + d] * latent[v * D + d];
            if (s > best) { best = s; bi = v; }
        }
        srm[t] = bi;
    }
    if (blockIdx.x == 0 && threadIdx.x >= 32 && threadIdx.x < 34) {
        int h = threadIdx.x - 32;
        float a0 = aggw[h * 3 + 0], a1 = aggw[h * 3 + 1], a2 = aggw[h * 3 + 2];
        float m = fmaxf(a0, fmaxf(a1, a2));
        float e0 = expf(a0 - m), e1 = expf(a1 - m), e2 = expf(a2 - m);
        float s = e0 + e1 + e2;
        g_w[h * 3 + 0] = e0 / s; g_w[h * 3 + 1] = e1 / s; g_w[h * 3 + 2] = e2 / s;
    }
    __syncthreads();
    int gid = blockIdx.x * blockDim.x + threadIdx.x;
    if (gid < NEDGE) {
        atomicAdd(&g_cnt[srm[etype[gid] - 1] * N_ENT + head[gid]], 1);
    } else if (gid < NVAL_ALL) {
        atomicAdd(&g_cnt[NBKT + uidx[gid - NEDGE]], 1);
    }
}

// ---------------- 3-kernel scan (measured cheap) ------------------------------
__global__ void k_scan1(const int* __restrict__ in, int* __restrict__ out,
                        int* __restrict__ bsum, int n) {
    __shared__ int sh[SCAN_B];
    int i = blockIdx.x * SCAN_B + threadIdx.x;
    int v = (i < n) ? in[i] : 0;
    sh[threadIdx.x] = v; __syncthreads();
    for (int o = 1; o < SCAN_B; o <<= 1) {
        int t = (threadIdx.x >= o) ? sh[threadIdx.x - o] : 0;
        __syncthreads();
        sh[threadIdx.x] += t;
        __syncthreads();
    }
    if (i < n) out[i] = sh[threadIdx.x] - v;
    if (threadIdx.x == SCAN_B - 1) bsum[blockIdx.x] = sh[threadIdx.x];
}
__global__ void k_scan2(int* __restrict__ bsum, int nb) {
    __shared__ int sh[SCAN_B];
    int v = (threadIdx.x < nb) ? bsum[threadIdx.x] : 0;
    sh[threadIdx.x] = v; __syncthreads();
    for (int o = 1; o < SCAN_B; o <<= 1) {
        int t = (threadIdx.x >= o) ? sh[threadIdx.x - o] : 0;
        __syncthreads();
        sh[threadIdx.x] += t;
        __syncthreads();
    }
    if (threadIdx.x < nb) bsum[threadIdx.x] = sh[threadIdx.x] - v;
}
__global__ void k_scan3(int* __restrict__ out, const int* __restrict__ bsum, int n) {
    int i = blockIdx.x * SCAN_B + threadIdx.x;
    if (i < n) out[i] += bsum[blockIdx.x];
}

// ---------------- fused scatter ------------------------------------------------
__global__ void k_scatter(const int* __restrict__ head, const int* __restrict__ tail,
                          const int* __restrict__ etype,
                          const int* __restrict__ uidx, const int* __restrict__ iidx,
                          const float* __restrict__ latent, const float* __restrict__ relw) {
    __shared__ int srm[NRELM1];
    if (threadIdx.x < NRELM1) {
        int t = threadIdx.x;
        float best = -1e30f; int bi = 0;
        for (int v = 0; v < NVIRT; v++) {
            float s = 0.f;
            for (int d = 0; d < D; d++) s += relw[t * D + d] * latent[v * D + d];
            if (s > best) { best = s; bi = v; }
        }
        srm[t] = bi;
    }
    __syncthreads();
    int gid = blockIdx.x * blockDim.x + threadIdx.x;
    if (gid < NEDGE) {
        int b = srm[etype[gid] - 1] * N_ENT + head[gid];
        int pos = g_off[b] + atomicAdd(&g_cur[b], 1);
        g_csr[pos] = tail[gid];
    } else if (gid < NVAL_ALL) {
        int j = gid - NEDGE;
        int b = NBKT + uidx[j];
        int pos = g_off[b] + atomicAdd(&g_cur[b], 1);
        g_csr[pos] = iidx[j];
    }
}

// ---------------- helpers -----------------------------------------------------
// sm_103 has NO redux.f32 — shuffle butterfly is the floor for fp32 warp sums.
__device__ __forceinline__ float warpsum(float v) {
    #pragma unroll
    for (int o = 16; o; o >>= 1) v += __shfl_xor_sync(0xffffffffu, v, o);
    return v;
}
__device__ __forceinline__ float warpdot2(float2 a, float2 b) {
    return warpsum(a.x * b.x + a.y * b.y);
}
// squash factor simplifies exactly: (sq/(sq+1))/max(sqrt(sq),eps) == sqrt(sq)/(sq+1)
__device__ __forceinline__ float2 squash_res(float2 acc, float inv, float2 e) {
    float2 a; a.x = acc.x * inv; a.y = acc.y * inv;
    float sq = warpdot2(a, a);
    float f = __fdividef(sqrtf(sq), sq + 1.0f);
    float2 r; r.x = a.x * f + e.x; r.y = a.y * f + e.y;
    return r;
}

// ---------------- entity hop: LWS x3 virt + agg + l2norm + residual, fused ----
__global__ void __launch_bounds__(256, 8) k_ent_hop(const float* __restrict__ ent,
                                                    float* __restrict__ ent_out,
                                                    float* __restrict__ out, int hop) {
    __shared__ float2 sh[8][CAP_E][32];          // 24 KB
    __shared__ float  shp[8][CAP_E];             // cached p1 per edge
    int gw = (blockIdx.x * blockDim.x + threadIdx.x) >> 5;
    int w = threadIdx.x >> 5;
    int lane = threadIdx.x & 31;
    if (gw >= N_ENT) return;
    int n = gw;
    float2 e = *(const float2*)(ent + (size_t)n * D + lane * 2);
    float2 agg; agg.x = 0.f; agg.y = 0.f;

    #pragma unroll
    for (int i = 0; i < NVIRT; i++) {
        int r = i * N_ENT + n;
        int beg = g_off[r];
        int end = g_off[r + 1];
        int deg = end - beg;
        float2 u3;
        if (deg == 0) {
            u3 = e;
        } else {
            float inv = __fdividef(1.0f, (float)deg);
            // iter 0: gather + cache
            float2 acc; acc.x = 0.f; acc.y = 0.f;
            for (int j = 0; j < deg; j++) {
                int t = g_csr[beg + j];
                float2 x = *(const float2*)(ent + (size_t)t * D + lane * 2);
                if (j < CAP_E) sh[w][j][lane] = x;
                acc.x += x.x; acc.y += x.y;
            }
            float2 u1 = squash_res(acc, inv, e);
            // iter 1: p1 = dot(u1,x); cache p1
            acc.x = 0.f; acc.y = 0.f;
            for (int j = 0; j < deg; j++) {
                float2 x;
                if (j < CAP_E) x = sh[w][j][lane];
                else {
                    int t = g_csr[beg + j];
                    x = *(const float2*)(ent + (size_t)t * D + lane * 2);
                }
                float p = warpdot2(u1, x);
                if (j < CAP_E && lane == 0) shp[w][j] = p;
                acc.x += p * x.x; acc.y += p * x.y;
            }
            float2 u2 = squash_res(acc, inv, e);
            // iter 2: c = p1^2 * dot(u2,x) — p1 from smem (1 dot chain, not 2)
            acc.x = 0.f; acc.y = 0.f;
            for (int j = 0; j < deg; j++) {
                float2 x; float p1;
                if (j < CAP_E) { x = sh[w][j][lane]; p1 = shp[w][j]; }
                else {
                    int t = g_csr[beg + j];
                    x = *(const float2*)(ent + (size_t)t * D + lane * 2);
                    p1 = warpdot2(u1, x);
                }
                float p2 = warpdot2(u2, x);
                float c = p1 * p1 * p2;
                acc.x += c * x.x; acc.y += c * x.y;
            }
            u3.x = acc.x * inv + e.x; u3.y = acc.y * inv + e.y;
        }
        float wv = g_w[hop * 3 + i];
        agg.x += wv * u3.x; agg.y += wv * u3.y;
    }

    float sq = warpdot2(agg, agg);
    float f = rsqrtf(fmaxf(sq, 1e-24f));
    float2 o2; o2.x = agg.x * f; o2.y = agg.y * f;
    *(float2*)(ent_out + (size_t)n * D + lane * 2) = o2;
    float* op = out + (size_t)n * D + lane * 2;
    if (hop == 0) {                   // out = orig ent + o2 (ent IS orig on hop 0)
        float2 v; v.x = e.x + o2.x; v.y = e.y + o2.y;
        *(float2*)op = v;
    } else {
        float2 prev = *(float2*)op;
        prev.x += o2.x; prev.y += o2.y;
        *(float2*)op = prev;
    }
}

// ---------------- user hop: fully fused ---------------------------------------
__global__ void __launch_bounds__(256, 8) k_usr_hop(const float* __restrict__ ent,
                                                    const float* __restrict__ usr,
                                                    float* __restrict__ usr_out,
                                                    float* __restrict__ out_usr, int hop) {
    __shared__ float2 sh[8][CAP_U][32];          // 24 KB
    int gtid = blockIdx.x * blockDim.x + threadIdx.x;
    // tail-of-pipeline zeroing of CSR-build state for the NEXT replay
    if (hop == 1 && gtid < NBKT_ALL) { g_cnt[gtid] = 0; g_cur[gtid] = 0; }
    int gw = gtid >> 5;
    int w = threadIdx.x >> 5;
    int lane = threadIdx.x & 31;
    if (gw >= N_USR) return;
    int n = gw;
    int beg = g_off[NBKT + n];
    int end = (n + 1 < N_USR) ? g_off[NBKT + n + 1] : NVAL_ALL;
    int deg = end - beg;
    float inv = __fdividef(1.0f, fmaxf((float)deg, 1.0f));
    float2 e = *(const float2*)(usr + (size_t)n * D + lane * 2);

    // iter 0: gather + cache
    float2 acc; acc.x = 0.f; acc.y = 0.f;
    for (int j = 0; j < deg; j++) {
        int t = g_csr[beg + j];
        float2 x = *(const float2*)(ent + (size_t)t * D + lane * 2);
        if (j < CAP_U) sh[w][j][lane] = x;
        acc.x += x.x; acc.y += x.y;
    }
    float2 u = squash_res(acc, inv, e);

    // iter 1
    acc.x = 0.f; acc.y = 0.f;
    for (int j = 0; j < deg; j++) {
        float2 x;
        if (j < CAP_U) x = sh[w][j][lane];
        else {
            int t = g_csr[beg + j];
            x = *(const float2*)(ent + (size_t)t * D + lane * 2);
        }
        float p = warpdot2(u, x);
        acc.x += p * x.x; acc.y += p * x.y;
    }
    u = squash_res(acc, inv, e);

    // iter 2 + l2norm + residual
    acc.x = 0.f; acc.y = 0.f;
    for (int j = 0; j < deg; j++) {
        float2 x;
        if (j < CAP_U) x = sh[w][j][lane];
        else {
            int t = g_csr[beg + j];
            x = *(const float2*)(ent + (size_t)t * D + lane * 2);
        }
        float p = warpdot2(u, x);
        acc.x += p * x.x; acc.y += p * x.y;
    }
    float2 v; v.x = acc.x * inv + e.x; v.y = acc.y * inv + e.y;
    float sq = warpdot2(v, v);
    float f = rsqrtf(fmaxf(sq, 1e-24f));
    float2 o2; o2.x = v.x * f; o2.y = v.y * f;
    *(float2*)(usr_out + (size_t)n * D + lane * 2) = o2;
    float* op = out_usr + (size_t)n * D + lane * 2;
    if (hop == 0) {
        float2 ov; ov.x = e.x + o2.x; ov.y = e.y + o2.y;
        *(float2*)op = ov;
    } else {
        float2 prev = *(float2*)op;
        prev.x += o2.x; prev.y += o2.y;
        *(float2*)op = prev;
    }
}

// ---------------- host orchestration ------------------------------------------
extern "C" void kernel_launch(void* const* d_in, const int* in_sizes, int n_in,
                              void* d_out, int out_size) {
    (void)in_sizes; (void)n_in; (void)out_size;
    const float* entity_emb = (const float*)d_in[0];
    const float* user_emb   = (const float*)d_in[1];
    const float* latent     = (const float*)d_in[2];
    const float* relw       = (const float*)d_in[3];
    const float* aggw       = (const float*)d_in[4];
    const int*   eidx       = (const int*)d_in[5];
    const int*   etype      = (const int*)d_in[6];
    const int*   uidx       = (const int*)d_in[7];
    const int*   iidx       = (const int*)d_in[8];
    float* out = (float*)d_out;
    const int* head = eidx;
    const int* tail = eidx + NEDGE;

    void *p_cnt, *p_off, *p_bsum, *p_entB, *p_entC, *p_usrB, *p_usrC;
    cudaGetSymbolAddress(&p_cnt,  g_cnt);
    cudaGetSymbolAddress(&p_off,  g_off);
    cudaGetSymbolAddress(&p_bsum, g_bsum);
    cudaGetSymbolAddress(&p_entB, g_entB);
    cudaGetSymbolAddress(&p_entC, g_entC);
    cudaGetSymbolAddress(&p_usrB, g_usrB);
    cudaGetSymbolAddress(&p_usrC, g_usrC);

    const int TPB = 256;
    const int CB  = (NVAL_ALL + TPB - 1) / TPB;
    const int NB  = (NBKT_ALL + SCAN_B - 1) / SCAN_B;   // 684
    const int RB  = (N_ENT * 32 + TPB - 1) / TPB;
    const int UB  = (N_USR * 32 + TPB - 1) / TPB;

    // 5-kernel prologue (counters pre-zeroed by previous replay's tail / static init)
    k_count<<<CB, TPB>>>(head, etype, uidx, latent, relw, aggw);
    k_scan1<<<NB, SCAN_B>>>((const int*)p_cnt, (int*)p_off, (int*)p_bsum, NBKT_ALL);
    k_scan2<<<1, SCAN_B>>>((int*)p_bsum, NB);
    k_scan3<<<NB, SCAN_B>>>((int*)p_off, (const int*)p_bsum, NBKT_ALL);
    k_scatter<<<CB, TPB>>>(head, tail, etype, uidx, iidx, latent, relw);

    // hop 0 (reads original embeddings directly) — k_ent_hop is launch #6
    k_ent_hop<<<RB, TPB>>>(entity_emb, (float*)p_entB, out, 0);
    k_usr_hop<<<UB, TPB>>>(entity_emb, user_emb, (float*)p_usrB, out + (size_t)N_ENT * D, 0);
    // hop 1 (tail of k_usr_hop zeroes counters for next replay)
    k_ent_hop<<<RB, TPB>>>((const float*)p_entB, (float*)p_entC, out, 1);
    k_usr_hop<<<UB, TPB>>>((const float*)p_entB, (const float*)p_usrB, (float*)p_usrC,
                           out + (size_t)N_ENT * D, 1);
}

// round 10
// speedup vs baseline: 1.0213x; 1.0213x over previous
#include <cuda_runtime.h>
#include <math.h>

#define N_ENT 200000
#define N_USR 100000
#define D     64
#define NEDGE 1500000
#define NINT  1000000
#define NVIRT 3
#define NRELM1 10
#define NBKT  (NVIRT * N_ENT)
#define NBKT_ALL (NBKT + N_USR)          // joint bucket space (entity then user)
#define NVAL_ALL (NEDGE + NINT)          // joint CSR value space
#define EPSV  1e-12f
#define SCAN_B 1024
#define CAP_E 12
#define CAP_U 20

// ---------------- scratch (static device globals; zero-initialized) ----------
__device__ float g_entB[(size_t)N_ENT * D];
__device__ float g_entC[(size_t)N_ENT * D];
__device__ float g_usrB[(size_t)N_USR * D];
__device__ float g_usrC[(size_t)N_USR * D];
__device__ int   g_csr[NVAL_ALL];        // entity tails then user items (joint)
__device__ int   g_cnt[NBKT_ALL];        // joint counts   (zeroed by tail of last hop)
__device__ int   g_off[NBKT_ALL + 1];    // joint exclusive-scan offsets
__device__ int   g_cur[NBKT_ALL];        // scatter cursors (zeroed by tail of last hop)
__device__ int   g_bsum[2048];
__device__ float g_w[2 * 3];             // softmaxed agg weights per hop

// ---------------- fused count: inline remap, entities + users, + softmax -----
__global__ void k_count(const int* __restrict__ head, const int* __restrict__ etype,
                        const int* __restrict__ uidx,
                        const float* __restrict__ latent, const float* __restrict__ relw,
                        const float* __restrict__ aggw) {
    __shared__ int srm[NRELM1];
    if (threadIdx.x < NRELM1) {
        int t = threadIdx.x;
        float best = -1e30f; int bi = 0;
        for (int v = 0; v < NVIRT; v++) {
            float s = 0.f;
            for (int d = 0; d < D; d++) s += relw[t * D + d] * latent[v * D + d];
            if (s > best) { best = s; bi = v; }
        }
        srm[t] = bi;
    }
    if (blockIdx.x == 0 && threadIdx.x >= 32 && threadIdx.x < 34) {
        int h = threadIdx.x - 32;
        float a0 = aggw[h * 3 + 0], a1 = aggw[h * 3 + 1], a2 = aggw[h * 3 + 2];
        float m = fmaxf(a0, fmaxf(a1, a2));
        float e0 = expf(a0 - m), e1 = expf(a1 - m), e2 = expf(a2 - m);
        float s = e0 + e1 + e2;
        g_w[h * 3 + 0] = e0 / s; g_w[h * 3 + 1] = e1 / s; g_w[h * 3 + 2] = e2 / s;
    }
    __syncthreads();
    int gid = blockIdx.x * blockDim.x + threadIdx.x;
    if (gid < NEDGE) {
        atomicAdd(&g_cnt[srm[etype[gid] - 1] * N_ENT + head[gid]], 1);
    } else if (gid < NVAL_ALL) {
        atomicAdd(&g_cnt[NBKT + uidx[gid - NEDGE]], 1);
    }
}

// ---------------- 3-kernel scan (measured cheap) ------------------------------
__global__ void k_scan1(const int* __restrict__ in, int* __restrict__ out,
                        int* __restrict__ bsum, int n) {
    __shared__ int sh[SCAN_B];
    int i = blockIdx.x * SCAN_B + threadIdx.x;
    int v = (i < n) ? in[i] : 0;
    sh[threadIdx.x] = v; __syncthreads();
    for (int o = 1; o < SCAN_B; o <<= 1) {
        int t = (threadIdx.x >= o) ? sh[threadIdx.x - o] : 0;
        __syncthreads();
        sh[threadIdx.x] += t;
        __syncthreads();
    }
    if (i < n) out[i] = sh[threadIdx.x] - v;
    if (threadIdx.x == SCAN_B - 1) bsum[blockIdx.x] = sh[threadIdx.x];
}
__global__ void k_scan2(int* __restrict__ bsum, int nb) {
    __shared__ int sh[SCAN_B];
    int v = (threadIdx.x < nb) ? bsum[threadIdx.x] : 0;
    sh[threadIdx.x] = v; __syncthreads();
    for (int o = 1; o < SCAN_B; o <<= 1) {
        int t = (threadIdx.x >= o) ? sh[threadIdx.x - o] : 0;
        __syncthreads();
        sh[threadIdx.x] += t;
        __syncthreads();
    }
    if (threadIdx.x < nb) bsum[threadIdx.x] = sh[threadIdx.x] - v;
}
__global__ void k_scan3(int* __restrict__ out, const int* __restrict__ bsum, int n) {
    int i = blockIdx.x * SCAN_B + threadIdx.x;
    if (i < n) out[i] += bsum[blockIdx.x];
}

// ---------------- fused scatter ------------------------------------------------
__global__ void k_scatter(const int* __restrict__ head, const int* __restrict__ tail,
                          const int* __restrict__ etype,
                          const int* __restrict__ uidx, const int* __restrict__ iidx,
                          const float* __restrict__ latent, const float* __restrict__ relw) {
    __shared__ int srm[NRELM1];
    if (threadIdx.x < NRELM1) {
        int t = threadIdx.x;
        float best = -1e30f; int bi = 0;
        for (int v = 0; v < NVIRT; v++) {
            float s = 0.f;
            for (int d = 0; d < D; d++) s += relw[t * D + d] * latent[v * D + d];
            if (s > best) { best = s; bi = v; }
        }
        srm[t] = bi;
    }
    __syncthreads();
    int gid = blockIdx.x * blockDim.x + threadIdx.x;
    if (gid < NEDGE) {
        int b = srm[etype[gid] - 1] * N_ENT + head[gid];
        int pos = g_off[b] + atomicAdd(&g_cur[b], 1);
        g_csr[pos] = tail[gid];
    } else if (gid < NVAL_ALL) {
        int j = gid - NEDGE;
        int b = NBKT + uidx[j];
        int pos = g_off[b] + atomicAdd(&g_cur[b], 1);
        g_csr[pos] = iidx[j];
    }
}

// ---------------- helpers -----------------------------------------------------
// sm_103 has NO redux.f32 — shuffle butterfly is the floor for fp32 warp sums.
__device__ __forceinline__ float warpsum(float v) {
    #pragma unroll
    for (int o = 16; o; o >>= 1) v += __shfl_xor_sync(0xffffffffu, v, o);
    return v;
}
__device__ __forceinline__ float warpdot2(float2 a, float2 b) {
    return warpsum(a.x * b.x + a.y * b.y);
}
__device__ __forceinline__ float2 squash_res(float2 acc, float inv, float2 e) {
    float2 a; a.x = acc.x * inv; a.y = acc.y * inv;
    float sq = warpdot2(a, a);
    float f = (sq / (sq + 1.0f)) / fmaxf(sqrtf(sq), EPSV);
    float2 r; r.x = a.x * f + e.x; r.y = a.y * f + e.y;
    return r;
}

// ---------------- entity hop: LWS x3 virt + agg + l2norm + residual, fused ----
__global__ void __launch_bounds__(256) k_ent_hop(const float* __restrict__ ent,
                                                 float* __restrict__ ent_out,
                                                 float* __restrict__ out, int hop) {
    __shared__ float2 sh[8][CAP_E][32];          // 24 KB
    int gw = (blockIdx.x * blockDim.x + threadIdx.x) >> 5;
    int w = threadIdx.x >> 5;
    int lane = threadIdx.x & 31;
    if (gw >= N_ENT) return;
    int n = gw;
    float2 e = *(const float2*)(ent + (size_t)n * D + lane * 2);
    float2 agg; agg.x = 0.f; agg.y = 0.f;

    #pragma unroll
    for (int i = 0; i < NVIRT; i++) {
        int r = i * N_ENT + n;
        int beg = g_off[r];
        int end = g_off[r + 1];
        int deg = end - beg;
        float2 u3;
        if (deg == 0) {
            u3 = e;
        } else {
            float inv = 1.0f / (float)deg;
            // iter 0: gather + cache
            float2 acc; acc.x = 0.f; acc.y = 0.f;
            for (int j = 0; j < deg; j++) {
                int t = g_csr[beg + j];
                float2 x = *(const float2*)(ent + (size_t)t * D + lane * 2);
                if (j < CAP_E) sh[w][j][lane] = x;
                acc.x += x.x; acc.y += x.y;
            }
            float2 u1 = squash_res(acc, inv, e);
            // iter 1
            acc.x = 0.f; acc.y = 0.f;
            for (int j = 0; j < deg; j++) {
                float2 x;
                if (j < CAP_E) x = sh[w][j][lane];
                else {
                    int t = g_csr[beg + j];
                    x = *(const float2*)(ent + (size_t)t * D + lane * 2);
                }
                float p = warpdot2(u1, x);
                acc.x += p * x.x; acc.y += p * x.y;
            }
            float2 u2 = squash_res(acc, inv, e);
            // iter 2
            acc.x = 0.f; acc.y = 0.f;
            for (int j = 0; j < deg; j++) {
                float2 x;
                if (j < CAP_E) x = sh[w][j][lane];
                else {
                    int t = g_csr[beg + j];
                    x = *(const float2*)(ent + (size_t)t * D + lane * 2);
                }
                float p1 = warpdot2(u1, x);
                float p2 = warpdot2(u2, x);
                float c = p1 * p1 * p2;
                acc.x += c * x.x; acc.y += c * x.y;
            }
            u3.x = acc.x * inv + e.x; u3.y = acc.y * inv + e.y;
        }
        float wv = g_w[hop * 3 + i];
        agg.x += wv * u3.x; agg.y += wv * u3.y;
    }

    float sq = warpdot2(agg, agg);
    float f = 1.0f / fmaxf(sqrtf(sq), EPSV);
    float2 o2; o2.x = agg.x * f; o2.y = agg.y * f;
    *(float2*)(ent_out + (size_t)n * D + lane * 2) = o2;
    float* op = out + (size_t)n * D + lane * 2;
    if (hop == 0) {                   // out = orig ent + o2 (ent IS orig on hop 0)
        float2 v; v.x = e.x + o2.x; v.y = e.y + o2.y;
        *(float2*)op = v;
    } else {
        float2 prev = *(float2*)op;
        prev.x += o2.x; prev.y += o2.y;
        *(float2*)op = prev;
    }
}

// ---------------- user hop: fully fused ---------------------------------------
__global__ void __launch_bounds__(256) k_usr_hop(const float* __restrict__ ent,
                                                 const float* __restrict__ usr,
                                                 float* __restrict__ usr_out,
                                                 float* __restrict__ out_usr, int hop) {
    __shared__ float2 sh[8][CAP_U][32];          // 40 KB
    int gtid = blockIdx.x * blockDim.x + threadIdx.x;
    // tail-of-pipeline zeroing of CSR-build state for the NEXT replay
    if (hop == 1 && gtid < NBKT_ALL) { g_cnt[gtid] = 0; g_cur[gtid] = 0; }
    int gw = gtid >> 5;
    int w = threadIdx.x >> 5;
    int lane = threadIdx.x & 31;
    if (gw >= N_USR) return;
    int n = gw;
    int beg = g_off[NBKT + n];
    int end = (n + 1 < N_USR) ? g_off[NBKT + n + 1] : NVAL_ALL;
    int deg = end - beg;
    float inv = 1.0f / fmaxf((float)deg, 1.0f);
    float2 e = *(const float2*)(usr + (size_t)n * D + lane * 2);

    // iter 0: gather + cache
    float2 acc; acc.x = 0.f; acc.y = 0.f;
    for (int j = 0; j < deg; j++) {
        int t = g_csr[beg + j];
        float2 x = *(const float2*)(ent + (size_t)t * D + lane * 2);
        if (j < CAP_U) sh[w][j][lane] = x;
        acc.x += x.x; acc.y += x.y;
    }
    float2 u = squash_res(acc, inv, e);

    // iter 1
    acc.x = 0.f; acc.y = 0.f;
    for (int j = 0; j < deg; j++) {
        float2 x;
        if (j < CAP_U) x = sh[w][j][lane];
        else {
            int t = g_csr[beg + j];
            x = *(const float2*)(ent + (size_t)t * D + lane * 2);
        }
        float p = warpdot2(u, x);
        acc.x += p * x.x; acc.y += p * x.y;
    }
    u = squash_res(acc, inv, e);

    // iter 2 + l2norm + residual
    acc.x = 0.f; acc.y = 0.f;
    for (int j = 0; j < deg; j++) {
        float2 x;
        if (j < CAP_U) x = sh[w][j][lane];
        else {
            int t = g_csr[beg + j];
            x = *(const float2*)(ent + (size_t)t * D + lane * 2);
        }
        float p = warpdot2(u, x);
        acc.x += p * x.x; acc.y += p * x.y;
    }
    float2 v; v.x = acc.x * inv + e.x; v.y = acc.y * inv + e.y;
    float sq = warpdot2(v, v);
    float f = 1.0f / fmaxf(sqrtf(sq), EPSV);
    float2 o2; o2.x = v.x * f; o2.y = v.y * f;
    *(float2*)(usr_out + (size_t)n * D + lane * 2) = o2;
    float* op = out_usr + (size_t)n * D + lane * 2;
    if (hop == 0) {
        float2 ov; ov.x = e.x + o2.x; ov.y = e.y + o2.y;
        *(float2*)op = ov;
    } else {
        float2 prev = *(float2*)op;
        prev.x += o2.x; prev.y += o2.y;
        *(float2*)op = prev;
    }
}

// ---------------- host orchestration ------------------------------------------
extern "C" void kernel_launch(void* const* d_in, const int* in_sizes, int n_in,
                              void* d_out, int out_size) {
    (void)in_sizes; (void)n_in; (void)out_size;
    const float* entity_emb = (const float*)d_in[0];
    const float* user_emb   = (const float*)d_in[1];
    const float* latent     = (const float*)d_in[2];
    const float* relw       = (const float*)d_in[3];
    const float* aggw       = (const float*)d_in[4];
    const int*   eidx       = (const int*)d_in[5];
    const int*   etype      = (const int*)d_in[6];
    const int*   uidx       = (const int*)d_in[7];
    const int*   iidx       = (const int*)d_in[8];
    float* out = (float*)d_out;
    const int* head = eidx;
    const int* tail = eidx + NEDGE;

    void *p_cnt, *p_off, *p_bsum, *p_entB, *p_entC, *p_usrB, *p_usrC;
    cudaGetSymbolAddress(&p_cnt,  g_cnt);
    cudaGetSymbolAddress(&p_off,  g_off);
    cudaGetSymbolAddress(&p_bsum, g_bsum);
    cudaGetSymbolAddress(&p_entB, g_entB);
    cudaGetSymbolAddress(&p_entC, g_entC);
    cudaGetSymbolAddress(&p_usrB, g_usrB);
    cudaGetSymbolAddress(&p_usrC, g_usrC);

    const int TPB = 256;
    const int CB  = (NVAL_ALL + TPB - 1) / TPB;
    const int NB  = (NBKT_ALL + SCAN_B - 1) / SCAN_B;   // 684
    const int RB  = (N_ENT * 32 + TPB - 1) / TPB;
    const int UB  = (N_USR * 32 + TPB - 1) / TPB;

    // 5-kernel prologue (counters pre-zeroed by previous replay's tail / static init)
    k_count<<<CB, TPB>>>(head, etype, uidx, latent, relw, aggw);
    k_scan1<<<NB, SCAN_B>>>((const int*)p_cnt, (int*)p_off, (int*)p_bsum, NBKT_ALL);
    k_scan2<<<1, SCAN_B>>>((int*)p_bsum, NB);
    k_scan3<<<NB, SCAN_B>>>((int*)p_off, (const int*)p_bsum, NBKT_ALL);
    k_scatter<<<CB, TPB>>>(head, tail, etype, uidx, iidx, latent, relw);

    // hop 0 (reads original embeddings directly) — k_ent_hop is launch #6
    k_ent_hop<<<RB, TPB>>>(entity_emb, (float*)p_entB, out, 0);
    k_usr_hop<<<UB, TPB>>>(entity_emb, user_emb, (float*)p_usrB, out + (size_t)N_ENT * D, 0);
    // hop 1 (tail of k_usr_hop zeroes counters for next replay)
    k_ent_hop<<<RB, TPB>>>((const float*)p_entB, (float*)p_entC, out, 1);
    k_usr_hop<<<UB, TPB>>>((const float*)p_entB, (const float*)p_usrB, (float*)p_usrC,
                           out + (size_t)N_ENT * D, 1);
}

// round 11
// speedup vs baseline: 1.2558x; 1.2296x over previous
#include <cuda_runtime.h>
#include <math.h>

#define N_ENT 200000
#define N_USR 100000
#define D     64
#define NEDGE 1500000
#define NINT  1000000
#define NVIRT 3
#define NRELM1 10
#define NBKT  (NVIRT * N_ENT)
#define NBKT_ALL (NBKT + N_USR)          // joint bucket space (entity then user)
#define NVAL_ALL (NEDGE + NINT)          // joint CSR value space
#define EPSV  1e-12f
#define SCAN_B 1024

// ---------------- scratch (static device globals; zero-initialized) ----------
__device__ float g_entB[(size_t)N_ENT * D];
__device__ float g_entC[(size_t)N_ENT * D];
__device__ float g_usrB[(size_t)N_USR * D];
__device__ float g_usrC[(size_t)N_USR * D];
__device__ int   g_csr[NVAL_ALL];        // entity tails then user items (joint)
__device__ int   g_cnt[NBKT_ALL];        // joint counts   (zeroed by tail of last hop)
__device__ int   g_off[NBKT_ALL + 1];    // joint exclusive-scan offsets
__device__ int   g_cur[NBKT_ALL];        // scatter cursors (zeroed by tail of last hop)
__device__ int   g_bsum[2048];
__device__ float g_w[2 * 3];             // softmaxed agg weights per hop

// ---------------- fused count: inline remap, entities + users, + softmax -----
__global__ void k_count(const int* __restrict__ head, const int* __restrict__ etype,
                        const int* __restrict__ uidx,
                        const float* __restrict__ latent, const float* __restrict__ relw,
                        const float* __restrict__ aggw) {
    __shared__ int srm[NRELM1];
    if (threadIdx.x < NRELM1) {
        int t = threadIdx.x;
        float best = -1e30f; int bi = 0;
        for (int v = 0; v < NVIRT; v++) {
            float s = 0.f;
            for (int d = 0; d < D; d++) s += relw[t * D + d] * latent[v * D + d];
            if (s > best) { best = s; bi = v; }
        }
        srm[t] = bi;
    }
    if (blockIdx.x == 0 && threadIdx.x >= 32 && threadIdx.x < 34) {
        int h = threadIdx.x - 32;
        float a0 = aggw[h * 3 + 0], a1 = aggw[h * 3 + 1], a2 = aggw[h * 3 + 2];
        float m = fmaxf(a0, fmaxf(a1, a2));
        float e0 = expf(a0 - m), e1 = expf(a1 - m), e2 = expf(a2 - m);
        float s = e0 + e1 + e2;
        g_w[h * 3 + 0] = e0 / s; g_w[h * 3 + 1] = e1 / s; g_w[h * 3 + 2] = e2 / s;
    }
    __syncthreads();
    int gid = blockIdx.x * blockDim.x + threadIdx.x;
    if (gid < NEDGE) {
        atomicAdd(&g_cnt[srm[etype[gid] - 1] * N_ENT + head[gid]], 1);
    } else if (gid < NVAL_ALL) {
        atomicAdd(&g_cnt[NBKT + uidx[gid - NEDGE]], 1);
    }
}

// ---------------- 3-kernel scan (measured cheap) ------------------------------
__global__ void k_scan1(const int* __restrict__ in, int* __restrict__ out,
                        int* __restrict__ bsum, int n) {
    __shared__ int sh[SCAN_B];
    int i = blockIdx.x * SCAN_B + threadIdx.x;
    int v = (i < n) ? in[i] : 0;
    sh[threadIdx.x] = v; __syncthreads();
    for (int o = 1; o < SCAN_B; o <<= 1) {
        int t = (threadIdx.x >= o) ? sh[threadIdx.x - o] : 0;
        __syncthreads();
        sh[threadIdx.x] += t;
        __syncthreads();
    }
    if (i < n) out[i] = sh[threadIdx.x] - v;
    if (threadIdx.x == SCAN_B - 1) bsum[blockIdx.x] = sh[threadIdx.x];
}
__global__ void k_scan2(int* __restrict__ bsum, int nb) {
    __shared__ int sh[SCAN_B];
    int v = (threadIdx.x < nb) ? bsum[threadIdx.x] : 0;
    sh[threadIdx.x] = v; __syncthreads();
    for (int o = 1; o < SCAN_B; o <<= 1) {
        int t = (threadIdx.x >= o) ? sh[threadIdx.x - o] : 0;
        __syncthreads();
        sh[threadIdx.x] += t;
        __syncthreads();
    }
    if (threadIdx.x < nb) bsum[threadIdx.x] = sh[threadIdx.x] - v;
}
__global__ void k_scan3(int* __restrict__ out, const int* __restrict__ bsum, int n) {
    int i = blockIdx.x * SCAN_B + threadIdx.x;
    if (i < n) out[i] += bsum[blockIdx.x];
}

// ---------------- fused scatter ------------------------------------------------
__global__ void k_scatter(const int* __restrict__ head, const int* __restrict__ tail,
                          const int* __restrict__ etype,
                          const int* __restrict__ uidx, const int* __restrict__ iidx,
                          const float* __restrict__ latent, const float* __restrict__ relw) {
    __shared__ int srm[NRELM1];
    if (threadIdx.x < NRELM1) {
        int t = threadIdx.x;
        float best = -1e30f; int bi = 0;
        for (int v = 0; v < NVIRT; v++) {
            float s = 0.f;
            for (int d = 0; d < D; d++) s += relw[t * D + d] * latent[v * D + d];
            if (s > best) { best = s; bi = v; }
        }
        srm[t] = bi;
    }
    __syncthreads();
    int gid = blockIdx.x * blockDim.x + threadIdx.x;
    if (gid < NEDGE) {
        int b = srm[etype[gid] - 1] * N_ENT + head[gid];
        int pos = g_off[b] + atomicAdd(&g_cur[b], 1);
        g_csr[pos] = tail[gid];
    } else if (gid < NVAL_ALL) {
        int j = gid - NEDGE;
        int b = NBKT + uidx[j];
        int pos = g_off[b] + atomicAdd(&g_cur[b], 1);
        g_csr[pos] = iidx[j];
    }
}

// ---------------- half-warp helpers (16 lanes per row, lane = 4 dims) ---------
__device__ __forceinline__ float dot16(float4 a, float4 b, unsigned mask) {
    float p = a.x * b.x + a.y * b.y + a.z * b.z + a.w * b.w;
    p += __shfl_xor_sync(mask, p, 8);
    p += __shfl_xor_sync(mask, p, 4);
    p += __shfl_xor_sync(mask, p, 2);
    p += __shfl_xor_sync(mask, p, 1);
    return p;
}
__device__ __forceinline__ float4 squash16(float4 acc, float inv, float4 e, unsigned mask) {
    float4 a;
    a.x = acc.x * inv; a.y = acc.y * inv; a.z = acc.z * inv; a.w = acc.w * inv;
    float sq = dot16(a, a, mask);
    float f = (sq / (sq + 1.0f)) / fmaxf(sqrtf(sq), EPSV);
    float4 r;
    r.x = a.x * f + e.x; r.y = a.y * f + e.y; r.z = a.z * f + e.z; r.w = a.w * f + e.w;
    return r;
}

// ---------------- entity hop: half-warp per row, 2 rows/warp ------------------
__global__ void __launch_bounds__(256) k_ent_hop(const float* __restrict__ ent,
                                                 float* __restrict__ ent_out,
                                                 float* __restrict__ out, int hop) {
    int gtid = blockIdx.x * blockDim.x + threadIdx.x;
    int gw = gtid >> 5;
    int half = (threadIdx.x >> 4) & 1;
    int l16 = threadIdx.x & 15;
    unsigned mask = half ? 0xFFFF0000u : 0x0000FFFFu;
    int n = gw * 2 + half;
    if (n >= N_ENT) return;
    const float* erow = ent + (size_t)n * D + l16 * 4;
    float4 e = *(const float4*)erow;
    float4 agg; agg.x = agg.y = agg.z = agg.w = 0.f;

    #pragma unroll
    for (int i = 0; i < NVIRT; i++) {
        int r = i * N_ENT + n;
        int beg = g_off[r];
        int deg = g_off[r + 1] - beg;
        float inv = 1.0f / fmaxf((float)deg, 1.0f);
        // iter 0: mean
        float4 acc; acc.x = acc.y = acc.z = acc.w = 0.f;
        for (int j = 0; j < deg; j++) {
            int t = g_csr[beg + j];
            float4 x = *(const float4*)(ent + (size_t)t * D + l16 * 4);
            acc.x += x.x; acc.y += x.y; acc.z += x.z; acc.w += x.w;
        }
        float4 u1 = squash16(acc, inv, e, mask);
        // iter 1: coef = dot(u1,x)
        acc.x = acc.y = acc.z = acc.w = 0.f;
        for (int j = 0; j < deg; j++) {
            int t = g_csr[beg + j];
            float4 x = *(const float4*)(ent + (size_t)t * D + l16 * 4);
            float p = dot16(u1, x, mask);
            acc.x += p * x.x; acc.y += p * x.y; acc.z += p * x.z; acc.w += p * x.w;
        }
        float4 u2 = squash16(acc, inv, e, mask);
        // iter 2: coef = dot(u1,x)^2 * dot(u2,x); no squash
        acc.x = acc.y = acc.z = acc.w = 0.f;
        for (int j = 0; j < deg; j++) {
            int t = g_csr[beg + j];
            float4 x = *(const float4*)(ent + (size_t)t * D + l16 * 4);
            float p1 = dot16(u1, x, mask);
            float p2 = dot16(u2, x, mask);
            float c = p1 * p1 * p2;
            acc.x += c * x.x; acc.y += c * x.y; acc.z += c * x.z; acc.w += c * x.w;
        }
        float wv = g_w[hop * 3 + i];
        agg.x += wv * (acc.x * inv + e.x);
        agg.y += wv * (acc.y * inv + e.y);
        agg.z += wv * (acc.z * inv + e.z);
        agg.w += wv * (acc.w * inv + e.w);
    }

    float sq = dot16(agg, agg, mask);
    float f = 1.0f / fmaxf(sqrtf(sq), EPSV);
    float4 o2; o2.x = agg.x * f; o2.y = agg.y * f; o2.z = agg.z * f; o2.w = agg.w * f;
    *(float4*)(ent_out + (size_t)n * D + l16 * 4) = o2;
    float* op = out + (size_t)n * D + l16 * 4;
    if (hop == 0) {                   // out = orig ent + o2 (ent IS orig on hop 0)
        float4 v; v.x = e.x + o2.x; v.y = e.y + o2.y; v.z = e.z + o2.z; v.w = e.w + o2.w;
        *(float4*)op = v;
    } else {
        float4 prev = *(float4*)op;
        prev.x += o2.x; prev.y += o2.y; prev.z += o2.z; prev.w += o2.w;
        *(float4*)op = prev;
    }
}

// ---------------- user hop: half-warp per user, 2 users/warp ------------------
__global__ void __launch_bounds__(256) k_usr_hop(const float* __restrict__ ent,
                                                 const float* __restrict__ usr,
                                                 float* __restrict__ usr_out,
                                                 float* __restrict__ out_usr, int hop) {
    int gtid = blockIdx.x * blockDim.x + threadIdx.x;
    // tail-of-pipeline zeroing of CSR-build state for the NEXT replay
    if (hop == 1 && gtid < NBKT_ALL) { g_cnt[gtid] = 0; g_cur[gtid] = 0; }
    int gw = gtid >> 5;
    int half = (threadIdx.x >> 4) & 1;
    int l16 = threadIdx.x & 15;
    unsigned mask = half ? 0xFFFF0000u : 0x0000FFFFu;
    int n = gw * 2 + half;
    if (n >= N_USR) return;
    int beg = g_off[NBKT + n];
    int deg = g_off[NBKT + n + 1] - beg;
    float inv = 1.0f / fmaxf((float)deg, 1.0f);
    float4 e = *(const float4*)(usr + (size_t)n * D + l16 * 4);

    // iter 0
    float4 acc; acc.x = acc.y = acc.z = acc.w = 0.f;
    for (int j = 0; j < deg; j++) {
        int t = g_csr[beg + j];
        float4 x = *(const float4*)(ent + (size_t)t * D + l16 * 4);
        acc.x += x.x; acc.y += x.y; acc.z += x.z; acc.w += x.w;
    }
    float4 u = squash16(acc, inv, e, mask);

    // iter 1
    acc.x = acc.y = acc.z = acc.w = 0.f;
    for (int j = 0; j < deg; j++) {
        int t = g_csr[beg + j];
        float4 x = *(const float4*)(ent + (size_t)t * D + l16 * 4);
        float p = dot16(u, x, mask);
        acc.x += p * x.x; acc.y += p * x.y; acc.z += p * x.z; acc.w += p * x.w;
    }
    u = squash16(acc, inv, e, mask);

    // iter 2 + l2norm + residual
    acc.x = acc.y = acc.z = acc.w = 0.f;
    for (int j = 0; j < deg; j++) {
        int t = g_csr[beg + j];
        float4 x = *(const float4*)(ent + (size_t)t * D + l16 * 4);
        float p = dot16(u, x, mask);
        acc.x += p * x.x; acc.y += p * x.y; acc.z += p * x.z; acc.w += p * x.w;
    }
    float4 v;
    v.x = acc.x * inv + e.x; v.y = acc.y * inv + e.y;
    v.z = acc.z * inv + e.z; v.w = acc.w * inv + e.w;
    float sq = dot16(v, v, mask);
    float f = 1.0f / fmaxf(sqrtf(sq), EPSV);
    float4 o2; o2.x = v.x * f; o2.y = v.y * f; o2.z = v.z * f; o2.w = v.w * f;
    *(float4*)(usr_out + (size_t)n * D + l16 * 4) = o2;
    float* op = out_usr + (size_t)n * D + l16 * 4;
    if (hop == 0) {
        float4 ov; ov.x = e.x + o2.x; ov.y = e.y + o2.y; ov.z = e.z + o2.z; ov.w = e.w + o2.w;
        *(float4*)op = ov;
    } else {
        float4 prev = *(float4*)op;
        prev.x += o2.x; prev.y += o2.y; prev.z += o2.z; prev.w += o2.w;
        *(float4*)op = prev;
    }
}

// ---------------- host orchestration ------------------------------------------
extern "C" void kernel_launch(void* const* d_in, const int* in_sizes, int n_in,
                              void* d_out, int out_size) {
    (void)in_sizes; (void)n_in; (void)out_size;
    const float* entity_emb = (const float*)d_in[0];
    const float* user_emb   = (const float*)d_in[1];
    const float* latent     = (const float*)d_in[2];
    const float* relw       = (const float*)d_in[3];
    const float* aggw       = (const float*)d_in[4];
    const int*   eidx       = (const int*)d_in[5];
    const int*   etype      = (const int*)d_in[6];
    const int*   uidx       = (const int*)d_in[7];
    const int*   iidx       = (const int*)d_in[8];
    float* out = (float*)d_out;
    const int* head = eidx;
    const int* tail = eidx + NEDGE;

    void *p_cnt, *p_off, *p_bsum, *p_entB, *p_entC, *p_usrB, *p_usrC;
    cudaGetSymbolAddress(&p_cnt,  g_cnt);
    cudaGetSymbolAddress(&p_off,  g_off);
    cudaGetSymbolAddress(&p_bsum, g_bsum);
    cudaGetSymbolAddress(&p_entB, g_entB);
    cudaGetSymbolAddress(&p_entC, g_entC);
    cudaGetSymbolAddress(&p_usrB, g_usrB);
    cudaGetSymbolAddress(&p_usrC, g_usrC);

    const int TPB = 256;
    const int CB  = (NVAL_ALL + TPB - 1) / TPB;
    const int NB  = (NBKT_ALL + SCAN_B - 1) / SCAN_B;   // 684
    const int RB  = ((N_ENT / 2) * 32 + TPB - 1) / TPB; // 2 rows per warp
    const int UB  = (((N_USR + 1) / 2) * 32 + TPB - 1) / TPB;

    // 5-kernel prologue (counters pre-zeroed by previous replay's tail / static init)
    k_count<<<CB, TPB>>>(head, etype, uidx, latent, relw, aggw);
    k_scan1<<<NB, SCAN_B>>>((const int*)p_cnt, (int*)p_off, (int*)p_bsum, NBKT_ALL);
    k_scan2<<<1, SCAN_B>>>((int*)p_bsum, NB);
    k_scan3<<<NB, SCAN_B>>>((int*)p_off, (const int*)p_bsum, NBKT_ALL);
    k_scatter<<<CB, TPB>>>(head, tail, etype, uidx, iidx, latent, relw);

    // hop 0 (reads original embeddings directly) — k_ent_hop is launch #6
    k_ent_hop<<<RB, TPB>>>(entity_emb, (float*)p_entB, out, 0);
    k_usr_hop<<<UB, TPB>>>(entity_emb, user_emb, (float*)p_usrB, out + (size_t)N_ENT * D, 0);
    // hop 1 (tail of k_usr_hop zeroes counters for next replay)
    k_ent_hop<<<RB, TPB>>>((const float*)p_entB, (float*)p_entC, out, 1);
    k_usr_hop<<<UB, TPB>>>((const float*)p_entB, (const float*)p_usrB, (float*)p_usrC,
                           out + (size_t)N_ENT * D, 1);
}

// round 12
// speedup vs baseline: 1.3149x; 1.0471x over previous
#include <cuda_runtime.h>
#include <math.h>

#define N_ENT 200000
#define N_USR 100000
#define D     64
#define NEDGE 1500000
#define NINT  1000000
#define NVIRT 3
#define NRELM1 10
#define NBKT  (NVIRT * N_ENT)
#define NBKT_ALL (NBKT + N_USR)          // joint bucket space (entity then user)
#define NVAL_ALL (NEDGE + NINT)          // joint CSR value space
#define EPSV  1e-12f
#define SCAN_B 1024
#define TPB   256
#define RBLK  ((N_ENT / 2) * 32 / TPB)   // 12500 entity blocks (2 rows/warp)
#define UBLK  ((N_USR / 2) * 32 / TPB)   // 6250 user blocks

// ---------------- scratch (static device globals; zero-initialized) ----------
__device__ float g_entB[(size_t)N_ENT * D];
__device__ float g_entC[(size_t)N_ENT * D];
__device__ float g_usrB[(size_t)N_USR * D];
__device__ float g_usrC[(size_t)N_USR * D];
__device__ int   g_csr[NVAL_ALL];        // entity tails then user items (joint)
__device__ int   g_cnt[NBKT_ALL];        // joint counts   (zeroed by tail of last hop)
__device__ int   g_off[NBKT_ALL + 1];    // joint exclusive-scan offsets
__device__ int   g_cur[NBKT_ALL];        // scatter cursors (zeroed by tail of last hop)
__device__ int   g_bsum[2048];
__device__ float g_w[2 * 3];             // softmaxed agg weights per hop

// ---------------- fused count: inline remap, entities + users, + softmax -----
__global__ void k_count(const int* __restrict__ head, const int* __restrict__ etype,
                        const int* __restrict__ uidx,
                        const float* __restrict__ latent, const float* __restrict__ relw,
                        const float* __restrict__ aggw) {
    __shared__ int srm[NRELM1];
    if (threadIdx.x < NRELM1) {
        int t = threadIdx.x;
        float best = -1e30f; int bi = 0;
        for (int v = 0; v < NVIRT; v++) {
            float s = 0.f;
            for (int d = 0; d < D; d++) s += relw[t * D + d] * latent[v * D + d];
            if (s > best) { best = s; bi = v; }
        }
        srm[t] = bi;
    }
    if (blockIdx.x == 0 && threadIdx.x >= 32 && threadIdx.x < 34) {
        int h = threadIdx.x - 32;
        float a0 = aggw[h * 3 + 0], a1 = aggw[h * 3 + 1], a2 = aggw[h * 3 + 2];
        float m = fmaxf(a0, fmaxf(a1, a2));
        float e0 = expf(a0 - m), e1 = expf(a1 - m), e2 = expf(a2 - m);
        float s = e0 + e1 + e2;
        g_w[h * 3 + 0] = e0 / s; g_w[h * 3 + 1] = e1 / s; g_w[h * 3 + 2] = e2 / s;
    }
    __syncthreads();
    int gid = blockIdx.x * blockDim.x + threadIdx.x;
    if (gid < NEDGE) {
        atomicAdd(&g_cnt[srm[etype[gid] - 1] * N_ENT + head[gid]], 1);
    } else if (gid < NVAL_ALL) {
        atomicAdd(&g_cnt[NBKT + uidx[gid - NEDGE]], 1);
    }
}

// ---------------- 3-kernel scan (measured cheap) ------------------------------
__global__ void k_scan1(const int* __restrict__ in, int* __restrict__ out,
                        int* __restrict__ bsum, int n) {
    __shared__ int sh[SCAN_B];
    int i = blockIdx.x * SCAN_B + threadIdx.x;
    int v = (i < n) ? in[i] : 0;
    sh[threadIdx.x] = v; __syncthreads();
    for (int o = 1; o < SCAN_B; o <<= 1) {
        int t = (threadIdx.x >= o) ? sh[threadIdx.x - o] : 0;
        __syncthreads();
        sh[threadIdx.x] += t;
        __syncthreads();
    }
    if (i < n) out[i] = sh[threadIdx.x] - v;
    if (threadIdx.x == SCAN_B - 1) bsum[blockIdx.x] = sh[threadIdx.x];
}
__global__ void k_scan2(int* __restrict__ bsum, int nb) {
    __shared__ int sh[SCAN_B];
    int v = (threadIdx.x < nb) ? bsum[threadIdx.x] : 0;
    sh[threadIdx.x] = v; __syncthreads();
    for (int o = 1; o < SCAN_B; o <<= 1) {
        int t = (threadIdx.x >= o) ? sh[threadIdx.x - o] : 0;
        __syncthreads();
        sh[threadIdx.x] += t;
        __syncthreads();
    }
    if (threadIdx.x < nb) bsum[threadIdx.x] = sh[threadIdx.x] - v;
}
__global__ void k_scan3(int* __restrict__ out, const int* __restrict__ bsum, int n) {
    int i = blockIdx.x * SCAN_B + threadIdx.x;
    if (i < n) out[i] += bsum[blockIdx.x];
}

// ---------------- fused scatter ------------------------------------------------
__global__ void k_scatter(const int* __restrict__ head, const int* __restrict__ tail,
                          const int* __restrict__ etype,
                          const int* __restrict__ uidx, const int* __restrict__ iidx,
                          const float* __restrict__ latent, const float* __restrict__ relw) {
    __shared__ int srm[NRELM1];
    if (threadIdx.x < NRELM1) {
        int t = threadIdx.x;
        float best = -1e30f; int bi = 0;
        for (int v = 0; v < NVIRT; v++) {
            float s = 0.f;
            for (int d = 0; d < D; d++) s += relw[t * D + d] * latent[v * D + d];
            if (s > best) { best = s; bi = v; }
        }
        srm[t] = bi;
    }
    __syncthreads();
    int gid = blockIdx.x * blockDim.x + threadIdx.x;
    if (gid < NEDGE) {
        int b = srm[etype[gid] - 1] * N_ENT + head[gid];
        int pos = g_off[b] + atomicAdd(&g_cur[b], 1);
        g_csr[pos] = tail[gid];
    } else if (gid < NVAL_ALL) {
        int j = gid - NEDGE;
        int b = NBKT + uidx[j];
        int pos = g_off[b] + atomicAdd(&g_cur[b], 1);
        g_csr[pos] = iidx[j];
    }
}

// ---------------- half-warp helpers (16 lanes per row, lane = 4 dims) ---------
__device__ __forceinline__ float dot16(float4 a, float4 b, unsigned mask) {
    float p = a.x * b.x + a.y * b.y + a.z * b.z + a.w * b.w;
    p += __shfl_xor_sync(mask, p, 8);
    p += __shfl_xor_sync(mask, p, 4);
    p += __shfl_xor_sync(mask, p, 2);
    p += __shfl_xor_sync(mask, p, 1);
    return p;
}
__device__ __forceinline__ float4 squash16(float4 acc, float inv, float4 e, unsigned mask) {
    float4 a;
    a.x = acc.x * inv; a.y = acc.y * inv; a.z = acc.z * inv; a.w = acc.w * inv;
    float sq = dot16(a, a, mask);
    float f = (sq / (sq + 1.0f)) / fmaxf(sqrtf(sq), EPSV);
    float4 r;
    r.x = a.x * f + e.x; r.y = a.y * f + e.y; r.z = a.z * f + e.z; r.w = a.w * f + e.w;
    return r;
}

// ---------------- fused hop: entity blocks [0,RBLK), user blocks [RBLK,RBLK+UBLK)
__global__ void __launch_bounds__(TPB) k_hop(const float* __restrict__ ent,
                                             float* __restrict__ ent_out,
                                             const float* __restrict__ usr,
                                             float* __restrict__ usr_out,
                                             float* __restrict__ out, int hop) {
    int half = (threadIdx.x >> 4) & 1;
    int l16 = threadIdx.x & 15;
    unsigned mask = half ? 0xFFFF0000u : 0x0000FFFFu;

    if (blockIdx.x < RBLK) {
        // ===== entity path =====
        int gw = (blockIdx.x * TPB + threadIdx.x) >> 5;
        int n = gw * 2 + half;
        float4 e = *(const float4*)(ent + (size_t)n * D + l16 * 4);
        float4 agg; agg.x = agg.y = agg.z = agg.w = 0.f;

        #pragma unroll
        for (int i = 0; i < NVIRT; i++) {
            int r = i * N_ENT + n;
            int beg = g_off[r];
            int deg = g_off[r + 1] - beg;
            float inv = 1.0f / fmaxf((float)deg, 1.0f);
            // iter 0: mean
            float4 acc; acc.x = acc.y = acc.z = acc.w = 0.f;
            for (int j = 0; j < deg; j++) {
                int t = g_csr[beg + j];
                float4 x = *(const float4*)(ent + (size_t)t * D + l16 * 4);
                acc.x += x.x; acc.y += x.y; acc.z += x.z; acc.w += x.w;
            }
            float4 u1 = squash16(acc, inv, e, mask);
            // iter 1: coef = dot(u1,x)
            acc.x = acc.y = acc.z = acc.w = 0.f;
            for (int j = 0; j < deg; j++) {
                int t = g_csr[beg + j];
                float4 x = *(const float4*)(ent + (size_t)t * D + l16 * 4);
                float p = dot16(u1, x, mask);
                acc.x += p * x.x; acc.y += p * x.y; acc.z += p * x.z; acc.w += p * x.w;
            }
            float4 u2 = squash16(acc, inv, e, mask);
            // iter 2: coef = dot(u1,x)^2 * dot(u2,x); no squash
            acc.x = acc.y = acc.z = acc.w = 0.f;
            for (int j = 0; j < deg; j++) {
                int t = g_csr[beg + j];
                float4 x = *(const float4*)(ent + (size_t)t * D + l16 * 4);
                float p1 = dot16(u1, x, mask);
                float p2 = dot16(u2, x, mask);
                float c = p1 * p1 * p2;
                acc.x += c * x.x; acc.y += c * x.y; acc.z += c * x.z; acc.w += c * x.w;
            }
            float wv = g_w[hop * 3 + i];
            agg.x += wv * (acc.x * inv + e.x);
            agg.y += wv * (acc.y * inv + e.y);
            agg.z += wv * (acc.z * inv + e.z);
            agg.w += wv * (acc.w * inv + e.w);
        }

        float sq = dot16(agg, agg, mask);
        float f = 1.0f / fmaxf(sqrtf(sq), EPSV);
        float4 o2; o2.x = agg.x * f; o2.y = agg.y * f; o2.z = agg.z * f; o2.w = agg.w * f;
        *(float4*)(ent_out + (size_t)n * D + l16 * 4) = o2;
        float* op = out + (size_t)n * D + l16 * 4;
        if (hop == 0) {               // out = orig ent + o2 (ent IS orig on hop 0)
            float4 v; v.x = e.x + o2.x; v.y = e.y + o2.y; v.z = e.z + o2.z; v.w = e.w + o2.w;
            *(float4*)op = v;
        } else {
            float4 prev = *(float4*)op;
            prev.x += o2.x; prev.y += o2.y; prev.z += o2.z; prev.w += o2.w;
            *(float4*)op = prev;
        }
    } else {
        // ===== user path =====
        int gtid_u = (blockIdx.x - RBLK) * TPB + threadIdx.x;
        // tail-of-pipeline zeroing of CSR-build state for the NEXT replay
        if (hop == 1 && gtid_u < NBKT_ALL) { g_cnt[gtid_u] = 0; g_cur[gtid_u] = 0; }
        int gw = gtid_u >> 5;
        int n = gw * 2 + half;
        float* out_usr = out + (size_t)N_ENT * D;
        int beg = g_off[NBKT + n];
        int deg = g_off[NBKT + n + 1] - beg;
        float inv = 1.0f / fmaxf((float)deg, 1.0f);
        float4 e = *(const float4*)(usr + (size_t)n * D + l16 * 4);

        // iter 0
        float4 acc; acc.x = acc.y = acc.z = acc.w = 0.f;
        for (int j = 0; j < deg; j++) {
            int t = g_csr[beg + j];
            float4 x = *(const float4*)(ent + (size_t)t * D + l16 * 4);
            acc.x += x.x; acc.y += x.y; acc.z += x.z; acc.w += x.w;
        }
        float4 u = squash16(acc, inv, e, mask);

        // iter 1
        acc.x = acc.y = acc.z = acc.w = 0.f;
        for (int j = 0; j < deg; j++) {
            int t = g_csr[beg + j];
            float4 x = *(const float4*)(ent + (size_t)t * D + l16 * 4);
            float p = dot16(u, x, mask);
            acc.x += p * x.x; acc.y += p * x.y; acc.z += p * x.z; acc.w += p * x.w;
        }
        u = squash16(acc, inv, e, mask);

        // iter 2 + l2norm + residual
        acc.x = acc.y = acc.z = acc.w = 0.f;
        for (int j = 0; j < deg; j++) {
            int t = g_csr[beg + j];
            float4 x = *(const float4*)(ent + (size_t)t * D + l16 * 4);
            float p = dot16(u, x, mask);
            acc.x += p * x.x; acc.y += p * x.y; acc.z += p * x.z; acc.w += p * x.w;
        }
        float4 v;
        v.x = acc.x * inv + e.x; v.y = acc.y * inv + e.y;
        v.z = acc.z * inv + e.z; v.w = acc.w * inv + e.w;
        float sq = dot16(v, v, mask);
        float f = 1.0f / fmaxf(sqrtf(sq), EPSV);
        float4 o2; o2.x = v.x * f; o2.y = v.y * f; o2.z = v.z * f; o2.w = v.w * f;
        *(float4*)(usr_out + (size_t)n * D + l16 * 4) = o2;
        float* op = out_usr + (size_t)n * D + l16 * 4;
        if (hop == 0) {
            float4 ov; ov.x = e.x + o2.x; ov.y = e.y + o2.y; ov.z = e.z + o2.z; ov.w = e.w + o2.w;
            *(float4*)op = ov;
        } else {
            float4 prev = *(float4*)op;
            prev.x += o2.x; prev.y += o2.y; prev.z += o2.z; prev.w += o2.w;
            *(float4*)op = prev;
        }
    }
}

// ---------------- host orchestration ------------------------------------------
extern "C" void kernel_launch(void* const* d_in, const int* in_sizes, int n_in,
                              void* d_out, int out_size) {
    (void)in_sizes; (void)n_in; (void)out_size;
    const float* entity_emb = (const float*)d_in[0];
    const float* user_emb   = (const float*)d_in[1];
    const float* latent     = (const float*)d_in[2];
    const float* relw       = (const float*)d_in[3];
    const float* aggw       = (const float*)d_in[4];
    const int*   eidx       = (const int*)d_in[5];
    const int*   etype      = (const int*)d_in[6];
    const int*   uidx       = (const int*)d_in[7];
    const int*   iidx       = (const int*)d_in[8];
    float* out = (float*)d_out;
    const int* head = eidx;
    const int* tail = eidx + NEDGE;

    void *p_cnt, *p_off, *p_bsum, *p_entB, *p_entC, *p_usrB, *p_usrC;
    cudaGetSymbolAddress(&p_cnt,  g_cnt);
    cudaGetSymbolAddress(&p_off,  g_off);
    cudaGetSymbolAddress(&p_bsum, g_bsum);
    cudaGetSymbolAddress(&p_entB, g_entB);
    cudaGetSymbolAddress(&p_entC, g_entC);
    cudaGetSymbolAddress(&p_usrB, g_usrB);
    cudaGetSymbolAddress(&p_usrC, g_usrC);

    const int CB  = (NVAL_ALL + TPB - 1) / TPB;
    const int NB  = (NBKT_ALL + SCAN_B - 1) / SCAN_B;   // 684

    // 5-kernel prologue (counters pre-zeroed by previous replay's tail / static init)
    k_count<<<CB, TPB>>>(head, etype, uidx, latent, relw, aggw);
    k_scan1<<<NB, SCAN_B>>>((const int*)p_cnt, (int*)p_off, (int*)p_bsum, NBKT_ALL);
    k_scan2<<<1, SCAN_B>>>((int*)p_bsum, NB);
    k_scan3<<<NB, SCAN_B>>>((int*)p_off, (const int*)p_bsum, NBKT_ALL);
    k_scatter<<<CB, TPB>>>(head, tail, etype, uidx, iidx, latent, relw);

    // hop 0 (reads original embeddings directly); entity + user concurrent
    k_hop<<<RBLK + UBLK, TPB>>>(entity_emb, (float*)p_entB,
                                user_emb, (float*)p_usrB, out, 0);
    // hop 1 (user path zeroes CSR-build state for next replay)
    k_hop<<<RBLK + UBLK, TPB>>>((const float*)p_entB, (float*)p_entC,
                                (const float*)p_usrB, (float*)p_usrC, out, 1);
}